// round 1
// baseline (speedup 1.0000x reference)
#include <cuda_runtime.h>
#include <math.h>

#define B_ 32
#define S_ 2048
#define H_ 1024
#define NROWS (2 * B_ * S_)   // 131072
#define WARPS_PER_BLOCK 8

// Scratch (allowed: __device__ globals, no allocation)
__device__ float g_rewards[NROWS];
__device__ float g_per_pair[B_];
__device__ int   g_accflag[B_];

// ---------------------------------------------------------------------------
// Kernel 1: rewards[row] = dot(hidden[row, :], w)   (HBM-bound, 512 MB read)
// One warp per row. Each lane: 8 independent float4 loads -> MLP=8.
// ---------------------------------------------------------------------------
__global__ void __launch_bounds__(WARPS_PER_BLOCK * 32)
reward_dot_kernel(const float* __restrict__ hs, const float* __restrict__ w) {
    __shared__ float4 sw[H_ / 4];
    for (int i = threadIdx.x; i < H_ / 4; i += blockDim.x)
        sw[i] = reinterpret_cast<const float4*>(w)[i];
    __syncthreads();

    const int warp = threadIdx.x >> 5;
    const int lane = threadIdx.x & 31;
    const int row  = blockIdx.x * WARPS_PER_BLOCK + warp;
    if (row >= NROWS) return;

    const float4* __restrict__ hp =
        reinterpret_cast<const float4*>(hs + (size_t)row * H_);

    float acc = 0.0f;
#pragma unroll
    for (int i = 0; i < H_ / 4 / 32; i++) {       // 8 iterations
        float4 h  = hp[lane + i * 32];
        float4 ww = sw[lane + i * 32];
        acc += h.x * ww.x + h.y * ww.y + h.z * ww.z + h.w * ww.w;
    }
#pragma unroll
    for (int o = 16; o; o >>= 1)
        acc += __shfl_xor_sync(0xffffffffu, acc, o);
    if (lane == 0) g_rewards[row] = acc;
}

// ---------------------------------------------------------------------------
// Kernel 2: per-pair index scan + masked sums. One block per pair (B_=32).
// Writes chosen/rejected scores directly; per_pair & acc flag to scratch.
// Deterministic (fixed reduction order within the block).
// ---------------------------------------------------------------------------
__device__ __forceinline__ float warp_sum(float v) {
#pragma unroll
    for (int o = 16; o; o >>= 1) v += __shfl_xor_sync(0xffffffffu, v, o);
    return v;
}
__device__ __forceinline__ int warp_sum_i(int v) {
#pragma unroll
    for (int o = 16; o; o >>= 1) v += __shfl_xor_sync(0xffffffffu, v, o);
    return v;
}

__global__ void __launch_bounds__(256)
pair_kernel(const int* __restrict__ ids, float* __restrict__ out) {
    const int b   = blockIdx.x;
    const int tid = threadIdx.x;
    const int* __restrict__ idc = ids + (size_t)b * S_;
    const int* __restrict__ idr = ids + (size_t)(B_ + b) * S_;
    const float* __restrict__ rwc = g_rewards + (size_t)b * S_;
    const float* __restrict__ rwr = g_rewards + (size_t)(B_ + b) * S_;

    __shared__ int sc, sr, sd;
    if (tid == 0) { sc = S_; sr = S_; sd = S_; }
    __syncthreads();

    int cmin = S_, rmin = S_, dmin = S_;
    for (int s = tid; s < S_; s += 256) {
        int ic = idc[s], ir = idr[s];
        if (ic == 0 && s < cmin) cmin = s;
        if (ir == 0 && s < rmin) rmin = s;
        if (ic != ir && s < dmin) dmin = s;
    }
    atomicMin(&sc, cmin);
    atomicMin(&sr, rmin);
    atomicMin(&sd, dmin);
    __syncthreads();

    const int  c_ind     = sc;               // default S_ == reference default
    const int  r_ind_pad = sr;
    const bool has_div   = sd < S_;
    const int  div_ind   = has_div ? sd : (S_ - 1);
    const int  r_ind     = has_div ? r_ind_pad : c_ind;
    const int  end_ind   = has_div ? max(c_ind, r_ind_pad) : S_;

    float lsum = 0.0f, csum = 0.0f, rsum = 0.0f;
    int   cnt_local = 0;
    for (int s = div_ind + tid; s < end_ind; s += 256) {
        float rc = rwc[s], rr = rwr[s];
        float x  = rc - rr;
        // log_sigmoid(x) = min(x,0) - log1p(exp(-|x|))
        lsum += fminf(x, 0.0f) - log1pf(expf(-fabsf(x)));
        csum += 1.0f / (1.0f + expf(-rc));
        rsum += 1.0f / (1.0f + expf(-rr));
        cnt_local++;
    }

    // block reduction (fixed order -> deterministic)
    __shared__ float sl[8], ss1[8], ss2[8];
    __shared__ int   sn[8];
    const int warp = tid >> 5, lane = tid & 31;
    float wl = warp_sum(lsum), wc = warp_sum(csum), wr = warp_sum(rsum);
    int   wn = warp_sum_i(cnt_local);
    if (lane == 0) { sl[warp] = wl; ss1[warp] = wc; ss2[warp] = wr; sn[warp] = wn; }
    __syncthreads();

    if (tid == 0) {
        float L = 0, C = 0, R = 0; int N = 0;
#pragma unroll
        for (int i = 0; i < 8; i++) { L += sl[i]; C += ss1[i]; R += ss2[i]; N += sn[i]; }
        float cnt = fmaxf((float)N, 1.0f);
        g_per_pair[b] = L / cnt;
        g_accflag[b]  = ((C - R) / cnt > 0.5f) ? 1 : 0;
        int ci = c_ind - 1; if (ci < 0) ci = 0;
        int ri = r_ind - 1; if (ri < 0) ri = 0;
        if (ci >= S_) ci = S_ - 1;
        if (ri >= S_) ri = S_ - 1;
        out[2 + b]       = rwc[ci];   // chosen_mean_score
        out[2 + B_ + b]  = rwr[ri];   // rejected_mean_score
    }
}

// ---------------------------------------------------------------------------
// Kernel 3: final deterministic scalar reduction (loss, acc)
// ---------------------------------------------------------------------------
__global__ void finalize_kernel(float* __restrict__ out) {
    const int lane = threadIdx.x;            // 32 threads, B_ = 32
    float pp = g_per_pair[lane];
    int   af = g_accflag[lane];
    float ls = warp_sum(pp);
    int   ac = warp_sum_i(af);
    if (lane == 0) {
        out[0] = -ls;          // loss
        out[1] = (float)ac;    // acc
    }
}

// ---------------------------------------------------------------------------
extern "C" void kernel_launch(void* const* d_in, const int* in_sizes, int n_in,
                              void* d_out, int out_size) {
    const int*   ids = (const int*)d_in[0];     // input_ids  (2B, S) int32
    const float* hs  = (const float*)d_in[1];   // hidden     (2B, S, H) f32
    const float* w   = (const float*)d_in[2];   // w          (H,) f32
    float* out = (float*)d_out;

    const int blocks = NROWS / WARPS_PER_BLOCK;   // 16384
    reward_dot_kernel<<<blocks, WARPS_PER_BLOCK * 32>>>(hs, w);
    pair_kernel<<<B_, 256>>>(ids, out);
    finalize_kernel<<<1, 32>>>(out);
}